// round 6
// baseline (speedup 1.0000x reference)
#include <cuda_runtime.h>
#include <math.h>

#define IMG_W 4096
#define IMG_H 4096
#define TW 64           // output tile width
#define TH 32           // output tile height
#define NT 256

// shared strides (floats), multiples of 4 for LDS.128
#define SA  76          // bufA: blur 36x68
#define SBs 68          // bufB: h-blurred tmp 40x68
#define SMs 72          // bufM: 34 rows (mag rows 1..34), mag col m at index m+3

__device__ __forceinline__ float4 vblur5(float g0, float g1, float g2, float g3, float g4,
                                         float4 a, float4 b, float4 c, float4 d, float4 e)
{
    float4 o;
    o.x = g0*a.x + g1*b.x + g2*c.x + g3*d.x + g4*e.x;
    o.y = g0*a.y + g1*b.y + g2*c.y + g3*d.y + g4*e.y;
    o.z = g0*a.z + g1*b.z + g2*c.z + g3*d.z + g4*e.z;
    o.w = g0*a.w + g1*b.w + g2*c.w + g3*d.w + g4*e.w;
    return o;
}

// h-blur 8 outputs from a 12-float window, write 2 float4 to bufB
__device__ __forceinline__ void hblur8(const float* __restrict__ w,
                                       float g0, float g1, float g2, float g3, float g4,
                                       float* __restrict__ dst)
{
    float4 o0, o1;
    o0.x = g0*w[0] + g1*w[1] + g2*w[2] + g3*w[3] + g4*w[4];
    o0.y = g0*w[1] + g1*w[2] + g2*w[3] + g3*w[4] + g4*w[5];
    o0.z = g0*w[2] + g1*w[3] + g2*w[4] + g3*w[5] + g4*w[6];
    o0.w = g0*w[3] + g1*w[4] + g2*w[5] + g3*w[6] + g4*w[7];
    o1.x = g0*w[4] + g1*w[5] + g2*w[6] + g3*w[7] + g4*w[8];
    o1.y = g0*w[5] + g1*w[6] + g2*w[7] + g3*w[8] + g4*w[9];
    o1.z = g0*w[6] + g1*w[7] + g2*w[8] + g3*w[9] + g4*w[10];
    o1.w = g0*w[7] + g1*w[8] + g2*w[9] + g3*w[10] + g4*w[11];
    *(float4*)(dst)     = o0;
    *(float4*)(dst + 4) = o1;
}

__global__ __launch_bounds__(NT, 4) void canny_kernel(
    const float* __restrict__ img,
    const float* __restrict__ gauss,
    float* __restrict__ out)
{
    __shared__ __align__(16) float bufA[36 * SA];
    __shared__ __align__(16) float bufB[40 * SBs];
    __shared__ __align__(16) float bufM[34 * SMs];

    const int tid = threadIdx.x;
    const int bx = blockIdx.x * TW;
    const int by = blockIdx.y * TH;
    const bool interior = (blockIdx.x >= 1 && blockIdx.x <= 62 &&
                           blockIdx.y >= 1 && blockIdx.y <= 126);

    const float g0 = gauss[0], g1 = gauss[1], g2 = gauss[2],
                g3 = gauss[3], g4 = gauss[4];

    // this thread's 4-wide x 2-tall output patch
    const int ox = 4 * (tid & 15);
    const int oy = 2 * (tid >> 4);

    // ---- S2 mapping: wide patches (1 row x 8 outputs), 320 items ----
    const int r20 = 8 * (tid >> 6) + (tid & 7);
    const int j20 = 8 * ((tid >> 3) & 7);
    const int i1  = tid + 256;                    // valid for tid < 64
    const int r21 = 8 * (i1 >> 6) + (i1 & 7);
    const int j21 = 8 * ((i1 >> 3) & 7);
    const bool s2b = (tid < 64);
    // narrow column (cols 64..67 of bufB), rows 0..39 -> tid 192..231
    const bool s2n = (tid >= 192 && tid < 232);
    const int rn = tid - 192;

    // ---- S3 mapping: 4-row x 1-col4 patches, 153 items ----
    const bool s3ok = (tid < 153);
    const int r3 = 4 * (tid / 17);                // 0..32
    const int j3 = 4 * (tid % 17);                // 0..64

    // ring pixel (mag coords: rows {1,34} x cols 0..65, cols {0,65} x rows 2..33)
    int mr = 1, mc = 0;
    const bool has_ring = (tid < 196);
    if (tid < 66)       { mr = 1;         mc = tid; }
    else if (tid < 132) { mr = 34;        mc = tid - 66; }
    else if (tid < 164) { mr = tid - 130; mc = 0; }
    else if (tid < 196) { mr = tid - 162; mc = 65; }

    float gxa[8], gya[8], maga[8];
    #pragma unroll
    for (int i = 0; i < 8; i++) { gxa[i] = 0.0f; gya[i] = 0.0f; maga[i] = 0.0f; }
    float ring_m = 0.0f;

    for (int c = 0; c < 3; c++) {
        const float* im = img + (size_t)c * (IMG_H * IMG_W);

        // ---- S2: h-blur straight from gmem -> bufB (40 rows x 68 cols) ----
        if (interior) {
            {
                const float* a = im + (size_t)(by - 4 + r20) * IMG_W + (bx - 4 + j20);
                float w[12];
                *(float4*)(w)     = *(const float4*)(a);
                *(float4*)(w + 4) = *(const float4*)(a + 4);
                *(float4*)(w + 8) = *(const float4*)(a + 8);
                hblur8(w, g0, g1, g2, g3, g4, &bufB[r20 * SBs + j20]);
            }
            if (s2b) {
                const float* a = im + (size_t)(by - 4 + r21) * IMG_W + (bx - 4 + j21);
                float w[12];
                *(float4*)(w)     = *(const float4*)(a);
                *(float4*)(w + 4) = *(const float4*)(a + 4);
                *(float4*)(w + 8) = *(const float4*)(a + 8);
                hblur8(w, g0, g1, g2, g3, g4, &bufB[r21 * SBs + j21]);
            }
            if (s2n) {
                const float* a = im + (size_t)(by - 4 + rn) * IMG_W + (bx + 60);
                float4 v0 = *(const float4*)(a);
                float4 v1 = *(const float4*)(a + 4);
                float4 o0;
                o0.x = g0*v0.x + g1*v0.y + g2*v0.z + g3*v0.w + g4*v1.x;
                o0.y = g0*v0.y + g1*v0.z + g2*v0.w + g3*v1.x + g4*v1.y;
                o0.z = g0*v0.z + g1*v0.w + g2*v1.x + g3*v1.y + g4*v1.z;
                o0.w = g0*v0.w + g1*v1.x + g2*v1.y + g3*v1.z + g4*v1.w;
                *(float4*)&bufB[rn * SBs + 64] = o0;
            }
        } else {
            {
                int iy = by - 4 + r20;
                bool oky = (iy >= 0 && iy < IMG_H);
                const float* a = im + (size_t)iy * IMG_W;
                float w[12];
                #pragma unroll
                for (int e = 0; e < 12; e++) {
                    int ix = bx - 4 + j20 + e;
                    w[e] = (oky && ix >= 0 && ix < IMG_W) ? a[ix] : 0.0f;
                }
                hblur8(w, g0, g1, g2, g3, g4, &bufB[r20 * SBs + j20]);
            }
            if (s2b) {
                int iy = by - 4 + r21;
                bool oky = (iy >= 0 && iy < IMG_H);
                const float* a = im + (size_t)iy * IMG_W;
                float w[12];
                #pragma unroll
                for (int e = 0; e < 12; e++) {
                    int ix = bx - 4 + j21 + e;
                    w[e] = (oky && ix >= 0 && ix < IMG_W) ? a[ix] : 0.0f;
                }
                hblur8(w, g0, g1, g2, g3, g4, &bufB[r21 * SBs + j21]);
            }
            if (s2n) {
                int iy = by - 4 + rn;
                bool oky = (iy >= 0 && iy < IMG_H);
                const float* a = im + (size_t)iy * IMG_W;
                float w[8];
                #pragma unroll
                for (int e = 0; e < 8; e++) {
                    int ix = bx + 60 + e;
                    w[e] = (oky && ix >= 0 && ix < IMG_W) ? a[ix] : 0.0f;
                }
                float4 o0;
                o0.x = g0*w[0] + g1*w[1] + g2*w[2] + g3*w[3] + g4*w[4];
                o0.y = g0*w[1] + g1*w[2] + g2*w[3] + g3*w[4] + g4*w[5];
                o0.z = g0*w[2] + g1*w[3] + g2*w[4] + g3*w[5] + g4*w[6];
                o0.w = g0*w[3] + g1*w[4] + g2*w[5] + g3*w[6] + g4*w[7];
                *(float4*)&bufB[rn * SBs + 64] = o0;
            }
        }
        __syncthreads();

        // ---- S3: vertical gaussian -> bufA (36 rows x 68 cols), 4-row patch ----
        if (s3ok) {
            const float* bcol = &bufB[r3 * SBs + j3];
            float* acol = &bufA[r3 * SA + j3];
            float4 t0 = *(const float4*)(bcol);
            float4 t1 = *(const float4*)(bcol + 1 * SBs);
            float4 t2 = *(const float4*)(bcol + 2 * SBs);
            float4 t3 = *(const float4*)(bcol + 3 * SBs);
            float4 t4 = *(const float4*)(bcol + 4 * SBs);
            #pragma unroll
            for (int k = 0; k < 4; k++) {
                float4 o = vblur5(g0, g1, g2, g3, g4, t0, t1, t2, t3, t4);
                if (!interior) {
                    int iy = by - 2 + r3 + k;
                    int ixb = bx - 2 + j3;
                    float* po = &o.x;
                    #pragma unroll
                    for (int cc = 0; cc < 4; cc++) {
                        int ix = ixb + cc;
                        if (!(ix >= 0 && ix < IMG_W && iy >= 0 && iy < IMG_H)) po[cc] = 0.0f;
                    }
                }
                *(float4*)(acol + k * SA) = o;
                if (k < 3) {
                    t0 = t1; t1 = t2; t2 = t3; t3 = t4;
                    t4 = *(const float4*)(bcol + (5 + k) * SBs);
                }
            }
        }
        __syncthreads();

        // ---- S4: merged sobel at output patch -> register accumulators ----
        {
            const float* b = &bufA[(oy + 1) * SA + ox];
            float r0[8], r1[8], r2[8], r3v[8];
            {
                float4 lo, hi;
                lo = *(const float4*)(b);            hi = *(const float4*)(b + 4);
                r0[0]=lo.x; r0[1]=lo.y; r0[2]=lo.z; r0[3]=lo.w; r0[4]=hi.x; r0[5]=hi.y; r0[6]=hi.z; r0[7]=hi.w;
                lo = *(const float4*)(b + SA);       hi = *(const float4*)(b + SA + 4);
                r1[0]=lo.x; r1[1]=lo.y; r1[2]=lo.z; r1[3]=lo.w; r1[4]=hi.x; r1[5]=hi.y; r1[6]=hi.z; r1[7]=hi.w;
                lo = *(const float4*)(b + 2*SA);     hi = *(const float4*)(b + 2*SA + 4);
                r2[0]=lo.x; r2[1]=lo.y; r2[2]=lo.z; r2[3]=lo.w; r2[4]=hi.x; r2[5]=hi.y; r2[6]=hi.z; r2[7]=hi.w;
            }
            #pragma unroll
            for (int cc = 0; cc < 4; cc++) {
                float b00 = r0[cc+1], b01 = r0[cc+2], b02 = r0[cc+3];
                float b10 = r1[cc+1],                 b12 = r1[cc+3];
                float b20 = r2[cc+1], b21 = r2[cc+2], b22 = r2[cc+3];
                float gxv = (b00 - b02) + 2.0f * (b10 - b12) + (b20 - b22);
                float gyv = (b00 - b20) + 2.0f * (b01 - b21) + (b02 - b22);
                gxa[cc] += gxv;
                gya[cc] += gyv;
                maga[cc] += sqrtf(gxv * gxv + gyv * gyv + 1e-8f);
            }
            {
                float4 lo = *(const float4*)(b + 3*SA);
                float4 hi = *(const float4*)(b + 3*SA + 4);
                r3v[0]=lo.x; r3v[1]=lo.y; r3v[2]=lo.z; r3v[3]=lo.w; r3v[4]=hi.x; r3v[5]=hi.y; r3v[6]=hi.z; r3v[7]=hi.w;
            }
            #pragma unroll
            for (int cc = 0; cc < 4; cc++) {
                float b00 = r1[cc+1], b01 = r1[cc+2], b02 = r1[cc+3];
                float b10 = r2[cc+1],                 b12 = r2[cc+3];
                float b20 = r3v[cc+1], b21 = r3v[cc+2], b22 = r3v[cc+3];
                float gxv = (b00 - b02) + 2.0f * (b10 - b12) + (b20 - b22);
                float gyv = (b00 - b20) + 2.0f * (b01 - b21) + (b02 - b22);
                gxa[4+cc] += gxv;
                gya[4+cc] += gyv;
                maga[4+cc] += sqrtf(gxv * gxv + gyv * gyv + 1e-8f);
            }
        }

        // ---- S4r: halo-ring mag pixel (register accumulated) ----
        if (has_ring) {
            const float* b = &bufA[(mr - 1) * SA + mc];
            float b00 = b[0],      b01 = b[1],          b02 = b[2];
            float b10 = b[SA],                          b12 = b[SA + 2];
            float b20 = b[2 * SA], b21 = b[2 * SA + 1], b22 = b[2 * SA + 2];
            float gxv = (b00 - b02) + 2.0f * (b10 - b12) + (b20 - b22);
            float gyv = (b00 - b20) + 2.0f * (b01 - b21) + (b02 - b22);
            float m = sqrtf(gxv * gxv + gyv * gyv + 1e-8f);
            if (!interior) {
                int iy = by - 2 + mr, ix = bx - 1 + mc;
                if (iy < 0 || iy >= IMG_H || ix < 0 || ix >= IMG_W) m = 0.0f;
            }
            ring_m += m;
        }
        __syncthreads();   // bufA/bufB free for next channel
    }

    // ---- publish mag to shared (once) ----
    #pragma unroll
    for (int rr = 0; rr < 2; rr++) {
        *(float4*)&bufM[(oy + 1 + rr) * SMs + ox + 4] =
            make_float4(maga[rr*4], maga[rr*4+1], maga[rr*4+2], maga[rr*4+3]);
    }
    if (has_ring) bufM[(mr - 1) * SMs + mc + 3] = ring_m;
    __syncthreads();

    // ---- S5: orientation, NMS, threshold, write ----
    const unsigned DYP = 0x00012221u;   // nibble ip -> dy+1
    const unsigned DXP = 0x21000122u;   // nibble ip -> dx+1
    const float RAD2DEG = (float)(180.0 / 3.14159);

    #pragma unroll
    for (int rr = 0; rr < 2; rr++) {
        float ov[4];
        #pragma unroll
        for (int cc = 0; cc < 4; cc++) {
            int y = oy + rr, x = ox + cc;
            float m  = maga[rr*4+cc];
            float t = atan2f(gya[rr*4+cc], gxa[rr*4+cc]) * RAD2DEG + 180.0f;
            int k = (int)rintf(t / 45.0f);
            int ip = k & 7;
            int dy = (int)((DYP >> (ip * 4)) & 7u) - 1;
            int dx = (int)((DXP >> (ip * 4)) & 7u) - 1;
            float mp = bufM[(y + 1 + dy) * SMs + (x + 4 + dx)];
            float mn = bufM[(y + 1 - dy) * SMs + (x + 4 - dx)];
            bool is_max = fminf(m - mp, m - mn) > 0.0f;
            ov[cc] = (is_max && m >= 6.0f && m <= 50.0f) ? 1.0f : 0.0f;
        }
        *(float4*)(out + (size_t)(by + oy + rr) * IMG_W + bx + ox) =
            make_float4(ov[0], ov[1], ov[2], ov[3]);
    }
}

extern "C" void kernel_launch(void* const* d_in, const int* in_sizes, int n_in,
                              void* d_out, int out_size) {
    const float* img   = (const float*)d_in[0];  // [1,3,4096,4096]
    const float* gauss = (const float*)d_in[1];  // [5]
    float* out = (float*)d_out;                  // [1,1,4096,4096]

    dim3 grid(IMG_W / TW, IMG_H / TH);
    canny_kernel<<<grid, NT>>>(img, gauss, out);
}

// round 7
// speedup vs baseline: 1.0792x; 1.0792x over previous
#include <cuda_runtime.h>
#include <math.h>

#define IMG_W 4096
#define IMG_H 4096
#define TW 64           // output tile width
#define TH 64           // output tile height
#define NT 512

// shared strides (floats)
#define SA  76          // bufA: img 72x72 then blur 68x68 (aliased)
#define SBs 68          // bufB: h-blurred tmp 72x68
#define SMs 72          // bufM: 66 rows x 72 (aliased over bufB)

__device__ __forceinline__ float4 vblur5(float g0, float g1, float g2, float g3, float g4,
                                         float4 a, float4 b, float4 c, float4 d, float4 e)
{
    float4 o;
    o.x = g0*a.x + g1*b.x + g2*c.x + g3*d.x + g4*e.x;
    o.y = g0*a.y + g1*b.y + g2*c.y + g3*d.y + g4*e.y;
    o.z = g0*a.z + g1*b.z + g2*c.z + g3*d.z + g4*e.z;
    o.w = g0*a.w + g1*b.w + g2*c.w + g3*d.w + g4*e.w;
    return o;
}

__global__ __launch_bounds__(NT, 2) void canny_kernel(
    const float* __restrict__ img,
    const float* __restrict__ gauss,
    float* __restrict__ out)
{
    __shared__ __align__(16) float bufA[72 * SA];   // 21888 B
    __shared__ __align__(16) float bufB[72 * SBs];  // 19584 B; bufM aliases this
    float* bufM = bufB;                              // 66*SMs = 4752 floats <= 72*SBs

    const int tid = threadIdx.x;
    const int bx = blockIdx.x * TW;
    const int by = blockIdx.y * TH;
    const bool interior = (blockIdx.x >= 1 && blockIdx.x <= 62 &&
                           blockIdx.y >= 1 && blockIdx.y <= 62);

    const float g0 = gauss[0], g1 = gauss[1], g2 = gauss[2],
                g3 = gauss[3], g4 = gauss[4];

    // this thread's 4-wide x 2-tall output patch
    const int ox = 4 * (tid & 15);        // 0..60
    const int oy = 2 * (tid >> 4);        // 0..62

    // ---- S2 mapping: wide patches (1 row x 8 outputs), 576 items ----
    // i -> row = 8*(i>>6)+(i&7): 8 consecutive lanes hit 8 different rows
    // (stride 76 -> bank starts {0,12,24,4,16,28,8,20}, conflict-free)
    const int r20 = 8 * (tid >> 6) + (tid & 7);
    const int j20 = 8 * ((tid >> 3) & 7);
    const int i1  = tid + 512;                    // valid for tid < 64
    const int r21 = 8 * (i1 >> 6) + (i1 & 7);
    const int j21 = 8 * ((i1 >> 3) & 7);
    const bool s2b = (tid < 64);
    // narrow column (bufB cols 64..67), rows 0..71 -> tid 64..135
    const bool s2n = (tid >= 64 && tid < 136);
    const int rn = tid - 64;

    // ---- S3 mapping: 4-row x 1-col4 patches, 289 items ----
    const bool s3ok = (tid < 289);
    const int r3 = 4 * (tid / 17);                // 0..64
    const int j3 = 4 * (tid % 17);                // 0..64

    // ring pixel in out coords (my,mx), 260 items
    int my = 0, mx = 0;
    const bool has_ring = (tid < 260);
    if (tid < 66)       { my = -1;        mx = tid - 1; }
    else if (tid < 132) { my = 64;        mx = tid - 67; }
    else if (tid < 196) { my = tid - 132; mx = -1; }
    else if (tid < 260) { my = tid - 196; mx = 64; }

    float gxa[8], gya[8], maga[8];
    #pragma unroll
    for (int i = 0; i < 8; i++) { gxa[i] = 0.0f; gya[i] = 0.0f; maga[i] = 0.0f; }
    float ring_m = 0.0f;

    for (int c = 0; c < 3; c++) {
        const float* im = img + (size_t)c * (IMG_H * IMG_W);

        // ---- S1: load img tile 72 rows x 72 cols into bufA (coalesced) ----
        if (interior) {
            #pragma unroll
            for (int it = 0; it < 3; it++) {
                int p = tid + it * NT;
                if (p < 1296) {                      // 72 rows x 18 float4
                    int r = p / 18;
                    int c4 = (p - r * 18) * 4;
                    float4 v = *(const float4*)(im + (size_t)(by - 4 + r) * IMG_W + (bx - 4) + c4);
                    *(float4*)&bufA[r * SA + c4] = v;
                }
            }
        } else {
            for (int p = tid; p < 72 * 72; p += NT) {
                int r = p / 72;
                int cc = p - r * 72;
                int iy = by - 4 + r, ix = bx - 4 + cc;
                float v = 0.0f;
                if (iy >= 0 && iy < IMG_H && ix >= 0 && ix < IMG_W)
                    v = im[(size_t)iy * IMG_W + ix];
                bufA[r * SA + cc] = v;
            }
        }
        __syncthreads();

        // ---- S2: horizontal gaussian -> bufB (72 rows x 68 cols) ----
        {
            {
                const float* a = &bufA[r20 * SA + j20];
                float4 v0 = *(const float4*)a;
                float4 v1 = *(const float4*)(a + 4);
                float4 v2 = *(const float4*)(a + 8);
                float w0=v0.x,w1=v0.y,w2=v0.z,w3=v0.w,w4=v1.x,w5=v1.y,w6=v1.z,w7=v1.w,
                      w8=v2.x,w9=v2.y,w10=v2.z,w11=v2.w;
                float4 o0, o1;
                o0.x = g0*w0 + g1*w1 + g2*w2 + g3*w3 + g4*w4;
                o0.y = g0*w1 + g1*w2 + g2*w3 + g3*w4 + g4*w5;
                o0.z = g0*w2 + g1*w3 + g2*w4 + g3*w5 + g4*w6;
                o0.w = g0*w3 + g1*w4 + g2*w5 + g3*w6 + g4*w7;
                o1.x = g0*w4 + g1*w5 + g2*w6 + g3*w7 + g4*w8;
                o1.y = g0*w5 + g1*w6 + g2*w7 + g3*w8 + g4*w9;
                o1.z = g0*w6 + g1*w7 + g2*w8 + g3*w9 + g4*w10;
                o1.w = g0*w7 + g1*w8 + g2*w9 + g3*w10 + g4*w11;
                *(float4*)&bufB[r20 * SBs + j20]     = o0;
                *(float4*)&bufB[r20 * SBs + j20 + 4] = o1;
            }
            if (s2b) {
                const float* a = &bufA[r21 * SA + j21];
                float4 v0 = *(const float4*)a;
                float4 v1 = *(const float4*)(a + 4);
                float4 v2 = *(const float4*)(a + 8);
                float w0=v0.x,w1=v0.y,w2=v0.z,w3=v0.w,w4=v1.x,w5=v1.y,w6=v1.z,w7=v1.w,
                      w8=v2.x,w9=v2.y,w10=v2.z,w11=v2.w;
                float4 o0, o1;
                o0.x = g0*w0 + g1*w1 + g2*w2 + g3*w3 + g4*w4;
                o0.y = g0*w1 + g1*w2 + g2*w3 + g3*w4 + g4*w5;
                o0.z = g0*w2 + g1*w3 + g2*w4 + g3*w5 + g4*w6;
                o0.w = g0*w3 + g1*w4 + g2*w5 + g3*w6 + g4*w7;
                o1.x = g0*w4 + g1*w5 + g2*w6 + g3*w7 + g4*w8;
                o1.y = g0*w5 + g1*w6 + g2*w7 + g3*w8 + g4*w9;
                o1.z = g0*w6 + g1*w7 + g2*w8 + g3*w9 + g4*w10;
                o1.w = g0*w7 + g1*w8 + g2*w9 + g3*w10 + g4*w11;
                *(float4*)&bufB[r21 * SBs + j21]     = o0;
                *(float4*)&bufB[r21 * SBs + j21 + 4] = o1;
            }
            if (s2n) {
                const float* a = &bufA[rn * SA + 64];
                float4 v0 = *(const float4*)a;
                float4 v1 = *(const float4*)(a + 4);
                float4 o0;
                o0.x = g0*v0.x + g1*v0.y + g2*v0.z + g3*v0.w + g4*v1.x;
                o0.y = g0*v0.y + g1*v0.z + g2*v0.w + g3*v1.x + g4*v1.y;
                o0.z = g0*v0.z + g1*v0.w + g2*v1.x + g3*v1.y + g4*v1.z;
                o0.w = g0*v0.w + g1*v1.x + g2*v1.y + g3*v1.z + g4*v1.w;
                *(float4*)&bufB[rn * SBs + 64] = o0;
            }
        }
        __syncthreads();

        // ---- S3: vertical gaussian -> bufA (68 rows x 68 cols), 4-row patch ----
        if (s3ok) {
            const float* bcol = &bufB[r3 * SBs + j3];
            float* acol = &bufA[r3 * SA + j3];
            float4 t0 = *(const float4*)(bcol);
            float4 t1 = *(const float4*)(bcol + 1 * SBs);
            float4 t2 = *(const float4*)(bcol + 2 * SBs);
            float4 t3 = *(const float4*)(bcol + 3 * SBs);
            float4 t4 = *(const float4*)(bcol + 4 * SBs);
            #pragma unroll
            for (int k = 0; k < 4; k++) {
                float4 o = vblur5(g0, g1, g2, g3, g4, t0, t1, t2, t3, t4);
                if (!interior) {
                    int iy = by - 2 + r3 + k;
                    int ixb = bx - 2 + j3;
                    float* po = &o.x;
                    #pragma unroll
                    for (int cc = 0; cc < 4; cc++) {
                        int ix = ixb + cc;
                        if (!(ix >= 0 && ix < IMG_W && iy >= 0 && iy < IMG_H)) po[cc] = 0.0f;
                    }
                }
                *(float4*)(acol + k * SA) = o;
                if (k < 3) {
                    t0 = t1; t1 = t2; t2 = t3; t3 = t4;
                    t4 = *(const float4*)(bcol + (5 + k) * SBs);
                }
            }
        }
        __syncthreads();

        // ---- S4: sobel at output patch -> register accumulators ----
        {
            const float* b = &bufA[(oy + 1) * SA + ox];
            float r0[8], r1[8], r2[8], r3v[8];
            {
                float4 lo, hi;
                lo = *(const float4*)(b);            hi = *(const float4*)(b + 4);
                r0[0]=lo.x; r0[1]=lo.y; r0[2]=lo.z; r0[3]=lo.w; r0[4]=hi.x; r0[5]=hi.y; r0[6]=hi.z; r0[7]=hi.w;
                lo = *(const float4*)(b + SA);       hi = *(const float4*)(b + SA + 4);
                r1[0]=lo.x; r1[1]=lo.y; r1[2]=lo.z; r1[3]=lo.w; r1[4]=hi.x; r1[5]=hi.y; r1[6]=hi.z; r1[7]=hi.w;
                lo = *(const float4*)(b + 2*SA);     hi = *(const float4*)(b + 2*SA + 4);
                r2[0]=lo.x; r2[1]=lo.y; r2[2]=lo.z; r2[3]=lo.w; r2[4]=hi.x; r2[5]=hi.y; r2[6]=hi.z; r2[7]=hi.w;
            }
            #pragma unroll
            for (int cc = 0; cc < 4; cc++) {
                float b00 = r0[cc+1], b01 = r0[cc+2], b02 = r0[cc+3];
                float b10 = r1[cc+1],                 b12 = r1[cc+3];
                float b20 = r2[cc+1], b21 = r2[cc+2], b22 = r2[cc+3];
                float gxv = (b00 - b02) + 2.0f * (b10 - b12) + (b20 - b22);
                float gyv = (b00 - b20) + 2.0f * (b01 - b21) + (b02 - b22);
                gxa[cc] += gxv;
                gya[cc] += gyv;
                maga[cc] += sqrtf(gxv * gxv + gyv * gyv + 1e-8f);
            }
            {
                float4 lo = *(const float4*)(b + 3*SA);
                float4 hi = *(const float4*)(b + 3*SA + 4);
                r3v[0]=lo.x; r3v[1]=lo.y; r3v[2]=lo.z; r3v[3]=lo.w; r3v[4]=hi.x; r3v[5]=hi.y; r3v[6]=hi.z; r3v[7]=hi.w;
            }
            #pragma unroll
            for (int cc = 0; cc < 4; cc++) {
                float b00 = r1[cc+1], b01 = r1[cc+2], b02 = r1[cc+3];
                float b10 = r2[cc+1],                 b12 = r2[cc+3];
                float b20 = r3v[cc+1], b21 = r3v[cc+2], b22 = r3v[cc+3];
                float gxv = (b00 - b02) + 2.0f * (b10 - b12) + (b20 - b22);
                float gyv = (b00 - b20) + 2.0f * (b01 - b21) + (b02 - b22);
                gxa[4+cc] += gxv;
                gya[4+cc] += gyv;
                maga[4+cc] += sqrtf(gxv * gxv + gyv * gyv + 1e-8f);
            }
        }

        // ---- S4r: halo-ring mag pixel (register accumulated) ----
        if (has_ring) {
            const float* b = &bufA[(my + 1) * SA + (mx + 1)];
            float b00 = b[0],      b01 = b[1],          b02 = b[2];
            float b10 = b[SA],                          b12 = b[SA + 2];
            float b20 = b[2 * SA], b21 = b[2 * SA + 1], b22 = b[2 * SA + 2];
            float gxv = (b00 - b02) + 2.0f * (b10 - b12) + (b20 - b22);
            float gyv = (b00 - b20) + 2.0f * (b01 - b21) + (b02 - b22);
            float m = sqrtf(gxv * gxv + gyv * gyv + 1e-8f);
            if (!interior) {
                int iy = by + my, ix = bx + mx;
                if (iy < 0 || iy >= IMG_H || ix < 0 || ix >= IMG_W) m = 0.0f;
            }
            ring_m += m;
        }
        __syncthreads();   // bufA/bufB free for next channel
    }

    // ---- publish mag to shared (bufM aliases bufB; bufB dead now) ----
    __syncthreads();       // everyone done reading bufB (already true) — cheap safety
    #pragma unroll
    for (int rr = 0; rr < 2; rr++) {
        *(float4*)&bufM[(oy + 1 + rr) * SMs + ox + 4] =
            make_float4(maga[rr*4], maga[rr*4+1], maga[rr*4+2], maga[rr*4+3]);
    }
    if (has_ring) bufM[(my + 1) * SMs + mx + 4] = ring_m;
    __syncthreads();

    // ---- S5: orientation, NMS, threshold, write ----
    const unsigned DYP = 0x00012221u;   // nibble ip -> dy+1
    const unsigned DXP = 0x21000122u;   // nibble ip -> dx+1
    const float RAD2DEG = (float)(180.0 / 3.14159);

    #pragma unroll
    for (int rr = 0; rr < 2; rr++) {
        float ov[4];
        #pragma unroll
        for (int cc = 0; cc < 4; cc++) {
            int y = oy + rr, x = ox + cc;
            float m  = maga[rr*4+cc];
            float t = atan2f(gya[rr*4+cc], gxa[rr*4+cc]) * RAD2DEG + 180.0f;
            int k = (int)rintf(t / 45.0f);
            int ip = k & 7;
            int dy = (int)((DYP >> (ip * 4)) & 7u) - 1;
            int dx = (int)((DXP >> (ip * 4)) & 7u) - 1;
            float mp = bufM[(y + 1 + dy) * SMs + (x + 4 + dx)];
            float mn = bufM[(y + 1 - dy) * SMs + (x + 4 - dx)];
            bool is_max = fminf(m - mp, m - mn) > 0.0f;
            ov[cc] = (is_max && m >= 6.0f && m <= 50.0f) ? 1.0f : 0.0f;
        }
        *(float4*)(out + (size_t)(by + oy + rr) * IMG_W + bx + ox) =
            make_float4(ov[0], ov[1], ov[2], ov[3]);
    }
}

extern "C" void kernel_launch(void* const* d_in, const int* in_sizes, int n_in,
                              void* d_out, int out_size) {
    const float* img   = (const float*)d_in[0];  // [1,3,4096,4096]
    const float* gauss = (const float*)d_in[1];  // [5]
    float* out = (float*)d_out;                  // [1,1,4096,4096]

    dim3 grid(IMG_W / TW, IMG_H / TH);
    canny_kernel<<<grid, NT>>>(img, gauss, out);
}

// round 9
// speedup vs baseline: 1.2268x; 1.1368x over previous
#include <cuda_runtime.h>
#include <stdint.h>
#include <math.h>

#define IMG_W 4096
#define IMG_H 4096
#define TW 64           // output tile width
#define TH 32           // output tile height
#define NT 256

// shared strides (floats), multiples of 4 for LDS.128
#define SA  76          // img tiles + blur buffer stride
#define SBs 68          // bufB: h-blurred tmp 40x68
#define SMs 72          // bufM view: 34 rows x 72 (aliases bufI0)

__device__ __forceinline__ float4 vblur5(float g0, float g1, float g2, float g3, float g4,
                                         float4 a, float4 b, float4 c, float4 d, float4 e)
{
    float4 o;
    o.x = g0*a.x + g1*b.x + g2*c.x + g3*d.x + g4*e.x;
    o.y = g0*a.y + g1*b.y + g2*c.y + g3*d.y + g4*e.y;
    o.z = g0*a.z + g1*b.z + g2*c.z + g3*d.z + g4*e.z;
    o.w = g0*a.w + g1*b.w + g2*c.w + g3*d.w + g4*e.w;
    return o;
}

__device__ __forceinline__ void cp_async16(void* dst_smem, const void* src)
{
    unsigned int d = (unsigned int)__cvta_generic_to_shared(dst_smem);
    asm volatile("cp.async.cg.shared.global [%0], [%1], 16;" :: "r"(d), "l"(src));
}

__global__ __launch_bounds__(NT, 4) void canny_kernel(
    const float* __restrict__ img,
    const float* __restrict__ gauss,
    float* __restrict__ out)
{
    __shared__ __align__(16) float bufI0[40 * SA];   // img tile, channel even
    __shared__ __align__(16) float bufI1[40 * SA];   // img tile, channel odd
    __shared__ __align__(16) float bufB[40 * SBs];   // h-blurred
    __shared__ __align__(16) float bufBl[36 * SA];   // v-blurred
    float* bufM = bufI0;                             // 34*SMs = 2448 <= 3040 floats

    const int tid = threadIdx.x;
    const int bx = blockIdx.x * TW;
    const int by = blockIdx.y * TH;
    const bool interior = (blockIdx.x >= 1 && blockIdx.x <= 62 &&
                           blockIdx.y >= 1 && blockIdx.y <= 126);

    const float g0 = gauss[0], g1 = gauss[1], g2 = gauss[2],
                g3 = gauss[3], g4 = gauss[4];

    // this thread's 4-wide x 2-tall output patch
    const int ox = 4 * (tid & 15);
    const int oy = 2 * (tid >> 4);

    // ---- S1 prefetch mapping: 720 float4 (40 rows x 18) ----
    const int s1r0 = tid / 18,          s1c0 = (tid - s1r0 * 18) * 4;
    const int t1 = tid + 256;
    const int s1r1 = t1 / 18,           s1c1 = (t1 - s1r1 * 18) * 4;
    const int t2s = tid + 512;
    const int s1r2 = t2s / 18,          s1c2 = (t2s - s1r2 * 18) * 4;
    const bool s1b2 = (t2s < 720);      // 208 threads

    // ---- S2 mapping: wide patches (1 row x 8 outputs), 320 items ----
    const int r20 = 8 * (tid >> 6) + (tid & 7);
    const int j20 = 8 * ((tid >> 3) & 7);
    const int i1  = tid + 256;                    // valid for tid < 64
    const int r21 = 8 * (i1 >> 6) + (i1 & 7);
    const int j21 = 8 * ((i1 >> 3) & 7);
    const bool s2b = (tid < 64);
    const bool s2n = (tid >= 192 && tid < 232);   // narrow col, rows 0..39
    const int rn = tid - 192;

    // ---- S3 mapping: 4-row x 1-col4 patches, 153 items ----
    const bool s3ok = (tid < 153);
    const int r3 = 4 * (tid / 17);
    const int j3 = 4 * (tid % 17);

    // ring pixel (mag coords: rows {1,34} x cols 0..65, cols {0,65} x rows 2..33)
    int mr = 1, mc = 0;
    const bool has_ring = (tid < 196);
    if (tid < 66)       { mr = 1;         mc = tid; }
    else if (tid < 132) { mr = 34;        mc = tid - 66; }
    else if (tid < 164) { mr = tid - 130; mc = 0; }
    else if (tid < 196) { mr = tid - 162; mc = 65; }

    float gxa[8], gya[8], maga[8];
    #pragma unroll
    for (int i = 0; i < 8; i++) { gxa[i] = 0.0f; gya[i] = 0.0f; maga[i] = 0.0f; }
    float ring_m = 0.0f;

    // ---- initial prefetch: channel 0 -> bufI0 ----
    if (interior) {
        const float* base = img + (size_t)(by - 4) * IMG_W + (bx - 4);
        cp_async16(&bufI0[s1r0 * SA + s1c0], base + (size_t)s1r0 * IMG_W + s1c0);
        cp_async16(&bufI0[s1r1 * SA + s1c1], base + (size_t)s1r1 * IMG_W + s1c1);
        if (s1b2)
            cp_async16(&bufI0[s1r2 * SA + s1c2], base + (size_t)s1r2 * IMG_W + s1c2);
        asm volatile("cp.async.commit_group;");
    } else {
        for (int p = tid; p < 2880; p += NT) {
            int r = p / 72;
            int cc = p - r * 72;
            int iy = by - 4 + r, ix = bx - 4 + cc;
            float v = 0.0f;
            if (iy >= 0 && iy < IMG_H && ix >= 0 && ix < IMG_W)
                v = img[(size_t)iy * IMG_W + ix];
            bufI0[r * SA + cc] = v;
        }
    }

    for (int c = 0; c < 3; c++) {
        float* bI = (c & 1) ? bufI1 : bufI0;

        if (interior) asm volatile("cp.async.wait_group 0;");
        __syncthreads();                 // bI ready for everyone

        // ---- prefetch next channel ----
        if (c < 2) {
            float* bN = ((c + 1) & 1) ? bufI1 : bufI0;
            const float* imn = img + (size_t)(c + 1) * (IMG_H * IMG_W);
            if (interior) {
                const float* base = imn + (size_t)(by - 4) * IMG_W + (bx - 4);
                cp_async16(&bN[s1r0 * SA + s1c0], base + (size_t)s1r0 * IMG_W + s1c0);
                cp_async16(&bN[s1r1 * SA + s1c1], base + (size_t)s1r1 * IMG_W + s1c1);
                if (s1b2)
                    cp_async16(&bN[s1r2 * SA + s1c2], base + (size_t)s1r2 * IMG_W + s1c2);
                asm volatile("cp.async.commit_group;");
            } else {
                for (int p = tid; p < 2880; p += NT) {
                    int r = p / 72;
                    int cc = p - r * 72;
                    int iy = by - 4 + r, ix = bx - 4 + cc;
                    float v = 0.0f;
                    if (iy >= 0 && iy < IMG_H && ix >= 0 && ix < IMG_W)
                        v = imn[(size_t)iy * IMG_W + ix];
                    bN[r * SA + cc] = v;
                }
            }
        }

        // ---- S2: horizontal gaussian -> bufB (40 rows x 68 cols) ----
        {
            {
                const float* a = &bI[r20 * SA + j20];
                float4 v0 = *(const float4*)a;
                float4 v1 = *(const float4*)(a + 4);
                float4 v2 = *(const float4*)(a + 8);
                float w0=v0.x,w1=v0.y,w2=v0.z,w3=v0.w,w4=v1.x,w5=v1.y,w6=v1.z,w7=v1.w,
                      w8=v2.x,w9=v2.y,w10=v2.z,w11=v2.w;
                float4 o0, o1;
                o0.x = g0*w0 + g1*w1 + g2*w2 + g3*w3 + g4*w4;
                o0.y = g0*w1 + g1*w2 + g2*w3 + g3*w4 + g4*w5;
                o0.z = g0*w2 + g1*w3 + g2*w4 + g3*w5 + g4*w6;
                o0.w = g0*w3 + g1*w4 + g2*w5 + g3*w6 + g4*w7;
                o1.x = g0*w4 + g1*w5 + g2*w6 + g3*w7 + g4*w8;
                o1.y = g0*w5 + g1*w6 + g2*w7 + g3*w8 + g4*w9;
                o1.z = g0*w6 + g1*w7 + g2*w8 + g3*w9 + g4*w10;
                o1.w = g0*w7 + g1*w8 + g2*w9 + g3*w10 + g4*w11;
                *(float4*)&bufB[r20 * SBs + j20]     = o0;
                *(float4*)&bufB[r20 * SBs + j20 + 4] = o1;
            }
            if (s2b) {
                const float* a = &bI[r21 * SA + j21];
                float4 v0 = *(const float4*)a;
                float4 v1 = *(const float4*)(a + 4);
                float4 v2 = *(const float4*)(a + 8);
                float w0=v0.x,w1=v0.y,w2=v0.z,w3=v0.w,w4=v1.x,w5=v1.y,w6=v1.z,w7=v1.w,
                      w8=v2.x,w9=v2.y,w10=v2.z,w11=v2.w;
                float4 o0, o1;
                o0.x = g0*w0 + g1*w1 + g2*w2 + g3*w3 + g4*w4;
                o0.y = g0*w1 + g1*w2 + g2*w3 + g3*w4 + g4*w5;
                o0.z = g0*w2 + g1*w3 + g2*w4 + g3*w5 + g4*w6;
                o0.w = g0*w3 + g1*w4 + g2*w5 + g3*w6 + g4*w7;
                o1.x = g0*w4 + g1*w5 + g2*w6 + g3*w7 + g4*w8;
                o1.y = g0*w5 + g1*w6 + g2*w7 + g3*w8 + g4*w9;
                o1.z = g0*w6 + g1*w7 + g2*w8 + g3*w9 + g4*w10;
                o1.w = g0*w7 + g1*w8 + g2*w9 + g3*w10 + g4*w11;
                *(float4*)&bufB[r21 * SBs + j21]     = o0;
                *(float4*)&bufB[r21 * SBs + j21 + 4] = o1;
            }
            if (s2n) {
                const float* a = &bI[rn * SA + 64];
                float4 v0 = *(const float4*)a;
                float4 v1 = *(const float4*)(a + 4);
                float4 o0;
                o0.x = g0*v0.x + g1*v0.y + g2*v0.z + g3*v0.w + g4*v1.x;
                o0.y = g0*v0.y + g1*v0.z + g2*v0.w + g3*v1.x + g4*v1.y;
                o0.z = g0*v0.z + g1*v0.w + g2*v1.x + g3*v1.y + g4*v1.z;
                o0.w = g0*v0.w + g1*v1.x + g2*v1.y + g3*v1.z + g4*v1.w;
                *(float4*)&bufB[rn * SBs + 64] = o0;
            }
        }
        __syncthreads();

        // ---- S3: vertical gaussian -> bufBl (36 rows x 68 cols), 4-row patch ----
        if (s3ok) {
            const float* bcol = &bufB[r3 * SBs + j3];
            float* acol = &bufBl[r3 * SA + j3];
            float4 t0 = *(const float4*)(bcol);
            float4 t1 = *(const float4*)(bcol + 1 * SBs);
            float4 t2 = *(const float4*)(bcol + 2 * SBs);
            float4 t3 = *(const float4*)(bcol + 3 * SBs);
            float4 t4 = *(const float4*)(bcol + 4 * SBs);
            #pragma unroll
            for (int k = 0; k < 4; k++) {
                float4 o = vblur5(g0, g1, g2, g3, g4, t0, t1, t2, t3, t4);
                if (!interior) {
                    int iy = by - 2 + r3 + k;
                    int ixb = bx - 2 + j3;
                    float* po = &o.x;
                    #pragma unroll
                    for (int cc = 0; cc < 4; cc++) {
                        int ix = ixb + cc;
                        if (!(ix >= 0 && ix < IMG_W && iy >= 0 && iy < IMG_H)) po[cc] = 0.0f;
                    }
                }
                *(float4*)(acol + k * SA) = o;
                if (k < 3) {
                    t0 = t1; t1 = t2; t2 = t3; t3 = t4;
                    t4 = *(const float4*)(bcol + (5 + k) * SBs);
                }
            }
        }
        __syncthreads();

        // ---- S4: sobel at output patch -> register accumulators ----
        {
            const float* b = &bufBl[(oy + 1) * SA + ox];
            float r0[8], r1[8], r2[8], r3v[8];
            {
                float4 lo, hi;
                lo = *(const float4*)(b);            hi = *(const float4*)(b + 4);
                r0[0]=lo.x; r0[1]=lo.y; r0[2]=lo.z; r0[3]=lo.w; r0[4]=hi.x; r0[5]=hi.y; r0[6]=hi.z; r0[7]=hi.w;
                lo = *(const float4*)(b + SA);       hi = *(const float4*)(b + SA + 4);
                r1[0]=lo.x; r1[1]=lo.y; r1[2]=lo.z; r1[3]=lo.w; r1[4]=hi.x; r1[5]=hi.y; r1[6]=hi.z; r1[7]=hi.w;
                lo = *(const float4*)(b + 2*SA);     hi = *(const float4*)(b + 2*SA + 4);
                r2[0]=lo.x; r2[1]=lo.y; r2[2]=lo.z; r2[3]=lo.w; r2[4]=hi.x; r2[5]=hi.y; r2[6]=hi.z; r2[7]=hi.w;
            }
            #pragma unroll
            for (int cc = 0; cc < 4; cc++) {
                float b00 = r0[cc+1], b01 = r0[cc+2], b02 = r0[cc+3];
                float b10 = r1[cc+1],                 b12 = r1[cc+3];
                float b20 = r2[cc+1], b21 = r2[cc+2], b22 = r2[cc+3];
                float gxv = (b00 - b02) + 2.0f * (b10 - b12) + (b20 - b22);
                float gyv = (b00 - b20) + 2.0f * (b01 - b21) + (b02 - b22);
                gxa[cc] += gxv;
                gya[cc] += gyv;
                maga[cc] += sqrtf(gxv * gxv + gyv * gyv + 1e-8f);
            }
            {
                float4 lo = *(const float4*)(b + 3*SA);
                float4 hi = *(const float4*)(b + 3*SA + 4);
                r3v[0]=lo.x; r3v[1]=lo.y; r3v[2]=lo.z; r3v[3]=lo.w; r3v[4]=hi.x; r3v[5]=hi.y; r3v[6]=hi.z; r3v[7]=hi.w;
            }
            #pragma unroll
            for (int cc = 0; cc < 4; cc++) {
                float b00 = r1[cc+1], b01 = r1[cc+2], b02 = r1[cc+3];
                float b10 = r2[cc+1],                 b12 = r2[cc+3];
                float b20 = r3v[cc+1], b21 = r3v[cc+2], b22 = r3v[cc+3];
                float gxv = (b00 - b02) + 2.0f * (b10 - b12) + (b20 - b22);
                float gyv = (b00 - b20) + 2.0f * (b01 - b21) + (b02 - b22);
                gxa[4+cc] += gxv;
                gya[4+cc] += gyv;
                maga[4+cc] += sqrtf(gxv * gxv + gyv * gyv + 1e-8f);
            }
        }

        // ---- S4r: halo-ring mag pixel (register accumulated) ----
        if (has_ring) {
            const float* b = &bufBl[(mr - 1) * SA + mc];
            float b00 = b[0],      b01 = b[1],          b02 = b[2];
            float b10 = b[SA],                          b12 = b[SA + 2];
            float b20 = b[2 * SA], b21 = b[2 * SA + 1], b22 = b[2 * SA + 2];
            float gxv = (b00 - b02) + 2.0f * (b10 - b12) + (b20 - b22);
            float gyv = (b00 - b20) + 2.0f * (b01 - b21) + (b02 - b22);
            float m = sqrtf(gxv * gxv + gyv * gyv + 1e-8f);
            if (!interior) {
                int iy = by - 2 + mr, ix = bx - 1 + mc;
                if (iy < 0 || iy >= IMG_H || ix < 0 || ix >= IMG_W) m = 0.0f;
            }
            ring_m += m;
        }
        __syncthreads();   // bufB/bufBl free for next channel
    }

    // ---- publish mag to shared (bufM aliases bufI0; dead now) ----
    #pragma unroll
    for (int rr = 0; rr < 2; rr++) {
        *(float4*)&bufM[(oy + 1 + rr) * SMs + ox + 4] =
            make_float4(maga[rr*4], maga[rr*4+1], maga[rr*4+2], maga[rr*4+3]);
    }
    if (has_ring) bufM[(mr - 1) * SMs + mc + 3] = ring_m;
    __syncthreads();

    // ---- S5: orientation, NMS, threshold, write ----
    const unsigned DYP = 0x00012221u;   // nibble ip -> dy+1
    const unsigned DXP = 0x21000122u;   // nibble ip -> dx+1
    const float RAD2DEG = (float)(180.0 / 3.14159);

    #pragma unroll
    for (int rr = 0; rr < 2; rr++) {
        float ov[4];
        #pragma unroll
        for (int cc = 0; cc < 4; cc++) {
            int y = oy + rr, x = ox + cc;
            float m  = maga[rr*4+cc];
            float t = atan2f(gya[rr*4+cc], gxa[rr*4+cc]) * RAD2DEG + 180.0f;
            int k = (int)rintf(t / 45.0f);
            int ip = k & 7;
            int dy = (int)((DYP >> (ip * 4)) & 7u) - 1;
            int dx = (int)((DXP >> (ip * 4)) & 7u) - 1;
            float mp = bufM[(y + 1 + dy) * SMs + (x + 4 + dx)];
            float mn = bufM[(y + 1 - dy) * SMs + (x + 4 - dx)];
            bool is_max = fminf(m - mp, m - mn) > 0.0f;
            ov[cc] = (is_max && m >= 6.0f && m <= 50.0f) ? 1.0f : 0.0f;
        }
        *(float4*)(out + (size_t)(by + oy + rr) * IMG_W + bx + ox) =
            make_float4(ov[0], ov[1], ov[2], ov[3]);
    }
}

extern "C" void kernel_launch(void* const* d_in, const int* in_sizes, int n_in,
                              void* d_out, int out_size) {
    const float* img   = (const float*)d_in[0];  // [1,3,4096,4096]
    const float* gauss = (const float*)d_in[1];  // [5]
    float* out = (float*)d_out;                  // [1,1,4096,4096]

    dim3 grid(IMG_W / TW, IMG_H / TH);
    canny_kernel<<<grid, NT>>>(img, gauss, out);
}

// round 10
// speedup vs baseline: 1.2970x; 1.0572x over previous
#include <cuda_runtime.h>
#include <stdint.h>
#include <math.h>

#define IMG_W 4096
#define IMG_H 4096
#define TW 64           // output tile width
#define TH 32           // output tile height
#define NT 256

// shared strides (floats), multiples of 4 for LDS.128
#define SA  76          // img tiles + blur buffer stride
#define SBs 68          // bufB: h-blurred tmp 40x68
#define SMs 72          // bufM view: 34 rows x 72 (aliases bufI0)

typedef unsigned long long ull;

__device__ __forceinline__ ull packf2(float a, float b)
{
    ull o;
    asm("mov.b64 %0, {%1, %2};" : "=l"(o) : "f"(a), "f"(b));
    return o;
}
__device__ __forceinline__ ull pmul(ull a, ull b)
{
    ull o;
    asm("mul.rn.f32x2 %0, %1, %2;" : "=l"(o) : "l"(a), "l"(b));
    return o;
}
__device__ __forceinline__ ull pfma(ull a, ull b, ull c)
{
    ull o;
    asm("fma.rn.f32x2 %0, %1, %2, %3;" : "=l"(o) : "l"(a), "l"(b), "l"(c));
    return o;
}

__device__ __forceinline__ float4 vblur5(float g0, float g1, float g2, float g3, float g4,
                                         float4 a, float4 b, float4 c, float4 d, float4 e)
{
    float4 o;
    o.x = g0*a.x + g1*b.x + g2*c.x + g3*d.x + g4*e.x;
    o.y = g0*a.y + g1*b.y + g2*c.y + g3*d.y + g4*e.y;
    o.z = g0*a.z + g1*b.z + g2*c.z + g3*d.z + g4*e.z;
    o.w = g0*a.w + g1*b.w + g2*c.w + g3*d.w + g4*e.w;
    return o;
}

__device__ __forceinline__ void cp_async16(void* dst_smem, const void* src)
{
    unsigned int d = (unsigned int)__cvta_generic_to_shared(dst_smem);
    asm volatile("cp.async.cg.shared.global [%0], [%1], 16;" :: "r"(d), "l"(src));
}

__global__ __launch_bounds__(NT, 4) void canny_kernel(
    const float* __restrict__ img,
    const float* __restrict__ gauss,
    float* __restrict__ out)
{
    __shared__ __align__(16) float bufI0[40 * SA];   // img tile, channel even
    __shared__ __align__(16) float bufI1[40 * SA];   // img tile, channel odd
    __shared__ __align__(16) float bufB[40 * SBs];   // h-blurred
    __shared__ __align__(16) float bufBl[36 * SA];   // v-blurred
    float* bufM = bufI0;                             // 34*SMs = 2448 <= 3040 floats

    const int tid = threadIdx.x;
    const int bx = blockIdx.x * TW;
    const int by = blockIdx.y * TH;
    const bool interior = (blockIdx.x >= 1 && blockIdx.x <= 62 &&
                           blockIdx.y >= 1 && blockIdx.y <= 126);

    const float g0 = gauss[0], g1 = gauss[1], g2 = gauss[2],
                g3 = gauss[3], g4 = gauss[4];
    const ull G0 = packf2(g0, g0), G1 = packf2(g1, g1), G2 = packf2(g2, g2),
              G3 = packf2(g3, g3), G4 = packf2(g4, g4);

    // this thread's 4-wide x 2-tall output patch
    const int ox = 4 * (tid & 15);
    const int oy = 2 * (tid >> 4);

    // ---- S1 prefetch mapping: 720 float4 (40 rows x 18) ----
    const int s1r0 = tid / 18,          s1c0 = (tid - s1r0 * 18) * 4;
    const int t1 = tid + 256;
    const int s1r1 = t1 / 18,           s1c1 = (t1 - s1r1 * 18) * 4;
    const int t2s = tid + 512;
    const int s1r2 = t2s / 18,          s1c2 = (t2s - s1r2 * 18) * 4;
    const bool s1b2 = (t2s < 720);      // 208 threads

    // ---- S2 mapping: wide patches (1 row x 8 outputs), 320 items ----
    const int r20 = 8 * (tid >> 6) + (tid & 7);
    const int j20 = 8 * ((tid >> 3) & 7);
    const int i1  = tid + 256;                    // valid for tid < 64
    const int r21 = 8 * (i1 >> 6) + (i1 & 7);
    const int j21 = 8 * ((i1 >> 3) & 7);
    const bool s2b = (tid < 64);
    const bool s2n = (tid >= 192 && tid < 232);   // narrow col, rows 0..39
    const int rn = tid - 192;

    // ---- S3 mapping: 4-row x 1-col4 patches, 153 items ----
    const bool s3ok = (tid < 153);
    const int r3 = 4 * (tid / 17);
    const int j3 = 4 * (tid % 17);

    // ring pixel (mag coords: rows {1,34} x cols 0..65, cols {0,65} x rows 2..33)
    int mr = 1, mc = 0;
    const bool has_ring = (tid < 196);
    if (tid < 66)       { mr = 1;         mc = tid; }
    else if (tid < 132) { mr = 34;        mc = tid - 66; }
    else if (tid < 164) { mr = tid - 130; mc = 0; }
    else if (tid < 196) { mr = tid - 162; mc = 65; }

    float gxa[8], gya[8], maga[8];
    #pragma unroll
    for (int i = 0; i < 8; i++) { gxa[i] = 0.0f; gya[i] = 0.0f; maga[i] = 0.0f; }
    float ring_m = 0.0f;

    // ---- initial prefetch: channel 0 -> bufI0 ----
    if (interior) {
        const float* base = img + (size_t)(by - 4) * IMG_W + (bx - 4);
        cp_async16(&bufI0[s1r0 * SA + s1c0], base + (size_t)s1r0 * IMG_W + s1c0);
        cp_async16(&bufI0[s1r1 * SA + s1c1], base + (size_t)s1r1 * IMG_W + s1c1);
        if (s1b2)
            cp_async16(&bufI0[s1r2 * SA + s1c2], base + (size_t)s1r2 * IMG_W + s1c2);
        asm volatile("cp.async.commit_group;");
    } else {
        for (int p = tid; p < 2880; p += NT) {
            int r = p / 72;
            int cc = p - r * 72;
            int iy = by - 4 + r, ix = bx - 4 + cc;
            float v = 0.0f;
            if (iy >= 0 && iy < IMG_H && ix >= 0 && ix < IMG_W)
                v = img[(size_t)iy * IMG_W + ix];
            bufI0[r * SA + cc] = v;
        }
    }

    #pragma unroll
    for (int c = 0; c < 3; c++) {
        float* bI = (c & 1) ? bufI1 : bufI0;

        if (interior) asm volatile("cp.async.wait_group 0;");
        __syncthreads();                 // bI ready for everyone

        // ---- prefetch next channel ----
        if (c < 2) {
            float* bN = ((c + 1) & 1) ? bufI1 : bufI0;
            const float* imn = img + (size_t)(c + 1) * (IMG_H * IMG_W);
            if (interior) {
                const float* base = imn + (size_t)(by - 4) * IMG_W + (bx - 4);
                cp_async16(&bN[s1r0 * SA + s1c0], base + (size_t)s1r0 * IMG_W + s1c0);
                cp_async16(&bN[s1r1 * SA + s1c1], base + (size_t)s1r1 * IMG_W + s1c1);
                if (s1b2)
                    cp_async16(&bN[s1r2 * SA + s1c2], base + (size_t)s1r2 * IMG_W + s1c2);
                asm volatile("cp.async.commit_group;");
            } else {
                for (int p = tid; p < 2880; p += NT) {
                    int r = p / 72;
                    int cc = p - r * 72;
                    int iy = by - 4 + r, ix = bx - 4 + cc;
                    float v = 0.0f;
                    if (iy >= 0 && iy < IMG_H && ix >= 0 && ix < IMG_W)
                        v = imn[(size_t)iy * IMG_W + ix];
                    bN[r * SA + cc] = v;
                }
            }
        }

        // ---- S2: horizontal gaussian -> bufB (40 rows x 68 cols) ----
        {
            {
                const float* a = &bI[r20 * SA + j20];
                float4 v0 = *(const float4*)a;
                float4 v1 = *(const float4*)(a + 4);
                float4 v2 = *(const float4*)(a + 8);
                float w0=v0.x,w1=v0.y,w2=v0.z,w3=v0.w,w4=v1.x,w5=v1.y,w6=v1.z,w7=v1.w,
                      w8=v2.x,w9=v2.y,w10=v2.z,w11=v2.w;
                float4 o0, o1;
                o0.x = g0*w0 + g1*w1 + g2*w2 + g3*w3 + g4*w4;
                o0.y = g0*w1 + g1*w2 + g2*w3 + g3*w4 + g4*w5;
                o0.z = g0*w2 + g1*w3 + g2*w4 + g3*w5 + g4*w6;
                o0.w = g0*w3 + g1*w4 + g2*w5 + g3*w6 + g4*w7;
                o1.x = g0*w4 + g1*w5 + g2*w6 + g3*w7 + g4*w8;
                o1.y = g0*w5 + g1*w6 + g2*w7 + g3*w8 + g4*w9;
                o1.z = g0*w6 + g1*w7 + g2*w8 + g3*w9 + g4*w10;
                o1.w = g0*w7 + g1*w8 + g2*w9 + g3*w10 + g4*w11;
                *(float4*)&bufB[r20 * SBs + j20]     = o0;
                *(float4*)&bufB[r20 * SBs + j20 + 4] = o1;
            }
            if (s2b) {
                const float* a = &bI[r21 * SA + j21];
                float4 v0 = *(const float4*)a;
                float4 v1 = *(const float4*)(a + 4);
                float4 v2 = *(const float4*)(a + 8);
                float w0=v0.x,w1=v0.y,w2=v0.z,w3=v0.w,w4=v1.x,w5=v1.y,w6=v1.z,w7=v1.w,
                      w8=v2.x,w9=v2.y,w10=v2.z,w11=v2.w;
                float4 o0, o1;
                o0.x = g0*w0 + g1*w1 + g2*w2 + g3*w3 + g4*w4;
                o0.y = g0*w1 + g1*w2 + g2*w3 + g3*w4 + g4*w5;
                o0.z = g0*w2 + g1*w3 + g2*w4 + g3*w5 + g4*w6;
                o0.w = g0*w3 + g1*w4 + g2*w5 + g3*w6 + g4*w7;
                o1.x = g0*w4 + g1*w5 + g2*w6 + g3*w7 + g4*w8;
                o1.y = g0*w5 + g1*w6 + g2*w7 + g3*w8 + g4*w9;
                o1.z = g0*w6 + g1*w7 + g2*w8 + g3*w9 + g4*w10;
                o1.w = g0*w7 + g1*w8 + g2*w9 + g3*w10 + g4*w11;
                *(float4*)&bufB[r21 * SBs + j21]     = o0;
                *(float4*)&bufB[r21 * SBs + j21 + 4] = o1;
            }
            if (s2n) {
                const float* a = &bI[rn * SA + 64];
                float4 v0 = *(const float4*)a;
                float4 v1 = *(const float4*)(a + 4);
                float4 o0;
                o0.x = g0*v0.x + g1*v0.y + g2*v0.z + g3*v0.w + g4*v1.x;
                o0.y = g0*v0.y + g1*v0.z + g2*v0.w + g3*v1.x + g4*v1.y;
                o0.z = g0*v0.z + g1*v0.w + g2*v1.x + g3*v1.y + g4*v1.z;
                o0.w = g0*v0.w + g1*v1.x + g2*v1.y + g3*v1.z + g4*v1.w;
                *(float4*)&bufB[rn * SBs + 64] = o0;
            }
        }
        __syncthreads();

        // ---- S3: vertical gaussian -> bufBl (36 rows x 68 cols), 4-row patch ----
        if (s3ok) {
            const float* bcol = &bufB[r3 * SBs + j3];
            float* acol = &bufBl[r3 * SA + j3];
            if (interior) {
                // packed f32x2: 10 ops per float4 instead of 20
                ulonglong2 t0 = *(const ulonglong2*)(bcol);
                ulonglong2 t1 = *(const ulonglong2*)(bcol + 1 * SBs);
                ulonglong2 t2 = *(const ulonglong2*)(bcol + 2 * SBs);
                ulonglong2 t3 = *(const ulonglong2*)(bcol + 3 * SBs);
                ulonglong2 t4 = *(const ulonglong2*)(bcol + 4 * SBs);
                #pragma unroll
                for (int k = 0; k < 4; k++) {
                    ulonglong2 o;
                    o.x = pfma(G4, t4.x, pfma(G3, t3.x, pfma(G2, t2.x,
                              pfma(G1, t1.x, pmul(G0, t0.x)))));
                    o.y = pfma(G4, t4.y, pfma(G3, t3.y, pfma(G2, t2.y,
                              pfma(G1, t1.y, pmul(G0, t0.y)))));
                    *(ulonglong2*)(acol + k * SA) = o;
                    if (k < 3) {
                        t0 = t1; t1 = t2; t2 = t3; t3 = t4;
                        t4 = *(const ulonglong2*)(bcol + (5 + k) * SBs);
                    }
                }
            } else {
                float4 t0 = *(const float4*)(bcol);
                float4 t1 = *(const float4*)(bcol + 1 * SBs);
                float4 t2 = *(const float4*)(bcol + 2 * SBs);
                float4 t3 = *(const float4*)(bcol + 3 * SBs);
                float4 t4 = *(const float4*)(bcol + 4 * SBs);
                #pragma unroll
                for (int k = 0; k < 4; k++) {
                    float4 o = vblur5(g0, g1, g2, g3, g4, t0, t1, t2, t3, t4);
                    int iy = by - 2 + r3 + k;
                    int ixb = bx - 2 + j3;
                    float* po = &o.x;
                    #pragma unroll
                    for (int cc = 0; cc < 4; cc++) {
                        int ix = ixb + cc;
                        if (!(ix >= 0 && ix < IMG_W && iy >= 0 && iy < IMG_H)) po[cc] = 0.0f;
                    }
                    *(float4*)(acol + k * SA) = o;
                    if (k < 3) {
                        t0 = t1; t1 = t2; t2 = t3; t3 = t4;
                        t4 = *(const float4*)(bcol + (5 + k) * SBs);
                    }
                }
            }
        }
        __syncthreads();

        // ---- S4: sobel at output patch -> register accumulators ----
        {
            const float* b = &bufBl[(oy + 1) * SA + ox];
            float r0[8], r1[8], r2[8], r3v[8];
            {
                float4 lo, hi;
                lo = *(const float4*)(b);            hi = *(const float4*)(b + 4);
                r0[0]=lo.x; r0[1]=lo.y; r0[2]=lo.z; r0[3]=lo.w; r0[4]=hi.x; r0[5]=hi.y; r0[6]=hi.z; r0[7]=hi.w;
                lo = *(const float4*)(b + SA);       hi = *(const float4*)(b + SA + 4);
                r1[0]=lo.x; r1[1]=lo.y; r1[2]=lo.z; r1[3]=lo.w; r1[4]=hi.x; r1[5]=hi.y; r1[6]=hi.z; r1[7]=hi.w;
                lo = *(const float4*)(b + 2*SA);     hi = *(const float4*)(b + 2*SA + 4);
                r2[0]=lo.x; r2[1]=lo.y; r2[2]=lo.z; r2[3]=lo.w; r2[4]=hi.x; r2[5]=hi.y; r2[6]=hi.z; r2[7]=hi.w;
            }
            #pragma unroll
            for (int cc = 0; cc < 4; cc++) {
                float b00 = r0[cc+1], b01 = r0[cc+2], b02 = r0[cc+3];
                float b10 = r1[cc+1],                 b12 = r1[cc+3];
                float b20 = r2[cc+1], b21 = r2[cc+2], b22 = r2[cc+3];
                float gxv = (b00 - b02) + 2.0f * (b10 - b12) + (b20 - b22);
                float gyv = (b00 - b20) + 2.0f * (b01 - b21) + (b02 - b22);
                gxa[cc] += gxv;
                gya[cc] += gyv;
                maga[cc] += sqrtf(gxv * gxv + gyv * gyv + 1e-8f);
            }
            {
                float4 lo = *(const float4*)(b + 3*SA);
                float4 hi = *(const float4*)(b + 3*SA + 4);
                r3v[0]=lo.x; r3v[1]=lo.y; r3v[2]=lo.z; r3v[3]=lo.w; r3v[4]=hi.x; r3v[5]=hi.y; r3v[6]=hi.z; r3v[7]=hi.w;
            }
            #pragma unroll
            for (int cc = 0; cc < 4; cc++) {
                float b00 = r1[cc+1], b01 = r1[cc+2], b02 = r1[cc+3];
                float b10 = r2[cc+1],                 b12 = r2[cc+3];
                float b20 = r3v[cc+1], b21 = r3v[cc+2], b22 = r3v[cc+3];
                float gxv = (b00 - b02) + 2.0f * (b10 - b12) + (b20 - b22);
                float gyv = (b00 - b20) + 2.0f * (b01 - b21) + (b02 - b22);
                gxa[4+cc] += gxv;
                gya[4+cc] += gyv;
                maga[4+cc] += sqrtf(gxv * gxv + gyv * gyv + 1e-8f);
            }
        }

        // ---- S4r: halo-ring mag pixel (register accumulated) ----
        if (has_ring) {
            const float* b = &bufBl[(mr - 1) * SA + mc];
            float b00 = b[0],      b01 = b[1],          b02 = b[2];
            float b10 = b[SA],                          b12 = b[SA + 2];
            float b20 = b[2 * SA], b21 = b[2 * SA + 1], b22 = b[2 * SA + 2];
            float gxv = (b00 - b02) + 2.0f * (b10 - b12) + (b20 - b22);
            float gyv = (b00 - b20) + 2.0f * (b01 - b21) + (b02 - b22);
            float m = sqrtf(gxv * gxv + gyv * gyv + 1e-8f);
            if (!interior) {
                int iy = by - 2 + mr, ix = bx - 1 + mc;
                if (iy < 0 || iy >= IMG_H || ix < 0 || ix >= IMG_W) m = 0.0f;
            }
            ring_m += m;
        }
        __syncthreads();   // bufB/bufBl free for next channel
    }

    // ---- publish mag to shared (bufM aliases bufI0; dead now) ----
    #pragma unroll
    for (int rr = 0; rr < 2; rr++) {
        *(float4*)&bufM[(oy + 1 + rr) * SMs + ox + 4] =
            make_float4(maga[rr*4], maga[rr*4+1], maga[rr*4+2], maga[rr*4+3]);
    }
    if (has_ring) bufM[(mr - 1) * SMs + mc + 3] = ring_m;
    __syncthreads();

    // ---- S5: orientation, NMS, threshold, write ----
    const unsigned DYP = 0x00012221u;   // nibble ip -> dy+1
    const unsigned DXP = 0x21000122u;   // nibble ip -> dx+1
    const float RAD2DEG = (float)(180.0 / 3.14159);

    #pragma unroll
    for (int rr = 0; rr < 2; rr++) {
        float ov[4];
        #pragma unroll
        for (int cc = 0; cc < 4; cc++) {
            int y = oy + rr, x = ox + cc;
            float m  = maga[rr*4+cc];
            float t = atan2f(gya[rr*4+cc], gxa[rr*4+cc]) * RAD2DEG + 180.0f;
            int k = (int)rintf(t / 45.0f);
            int ip = k & 7;
            int dy = (int)((DYP >> (ip * 4)) & 7u) - 1;
            int dx = (int)((DXP >> (ip * 4)) & 7u) - 1;
            float mp = bufM[(y + 1 + dy) * SMs + (x + 4 + dx)];
            float mn = bufM[(y + 1 - dy) * SMs + (x + 4 - dx)];
            bool is_max = fminf(m - mp, m - mn) > 0.0f;
            ov[cc] = (is_max && m >= 6.0f && m <= 50.0f) ? 1.0f : 0.0f;
        }
        *(float4*)(out + (size_t)(by + oy + rr) * IMG_W + bx + ox) =
            make_float4(ov[0], ov[1], ov[2], ov[3]);
    }
}

extern "C" void kernel_launch(void* const* d_in, const int* in_sizes, int n_in,
                              void* d_out, int out_size) {
    const float* img   = (const float*)d_in[0];  // [1,3,4096,4096]
    const float* gauss = (const float*)d_in[1];  // [5]
    float* out = (float*)d_out;                  // [1,1,4096,4096]

    dim3 grid(IMG_W / TW, IMG_H / TH);
    canny_kernel<<<grid, NT>>>(img, gauss, out);
}

// round 11
// speedup vs baseline: 1.3106x; 1.0105x over previous
#include <cuda_runtime.h>
#include <stdint.h>
#include <math.h>

#define IMG_W 4096
#define IMG_H 4096
#define TW 64           // output tile width
#define TH 32           // output tile height
#define NT 256

// shared strides (floats), multiples of 4 for LDS.128
#define SA  76          // img tiles + blur buffer stride
#define SBs 68          // bufB: h-blurred tmp 40x68
#define SMs 72          // bufM view: 34 rows x 72 (aliases bufI0)

typedef unsigned long long ull;

__device__ __forceinline__ ull packf2(float a, float b)
{
    ull o;
    asm("mov.b64 %0, {%1, %2};" : "=l"(o) : "f"(a), "f"(b));
    return o;
}
__device__ __forceinline__ ull pmul(ull a, ull b)
{
    ull o;
    asm("mul.rn.f32x2 %0, %1, %2;" : "=l"(o) : "l"(a), "l"(b));
    return o;
}
__device__ __forceinline__ ull pfma(ull a, ull b, ull c)
{
    ull o;
    asm("fma.rn.f32x2 %0, %1, %2, %3;" : "=l"(o) : "l"(a), "l"(b), "l"(c));
    return o;
}

__device__ __forceinline__ float4 vblur5(float g0, float g1, float g2, float g3, float g4,
                                         float4 a, float4 b, float4 c, float4 d, float4 e)
{
    float4 o;
    o.x = g0*a.x + g1*b.x + g2*c.x + g3*d.x + g4*e.x;
    o.y = g0*a.y + g1*b.y + g2*c.y + g3*d.y + g4*e.y;
    o.z = g0*a.z + g1*b.z + g2*c.z + g3*d.z + g4*e.z;
    o.w = g0*a.w + g1*b.w + g2*c.w + g3*d.w + g4*e.w;
    return o;
}

__device__ __forceinline__ void cp_async16(void* dst_smem, const void* src)
{
    unsigned int d = (unsigned int)__cvta_generic_to_shared(dst_smem);
    asm volatile("cp.async.cg.shared.global [%0], [%1], 16;" :: "r"(d), "l"(src));
}

__global__ __launch_bounds__(NT, 4) void canny_kernel(
    const float* __restrict__ img,
    const float* __restrict__ gauss,
    float* __restrict__ out)
{
    __shared__ __align__(16) float bufI0[40 * SA];   // img tile, channel even
    __shared__ __align__(16) float bufI1[40 * SA];   // img tile, channel odd
    __shared__ __align__(16) float bufB[40 * SBs];   // h-blurred
    __shared__ __align__(16) float bufBl[36 * SA];   // v-blurred
    float* bufM = bufI0;                             // 34*SMs = 2448 <= 3040 floats

    const int tid = threadIdx.x;
    const int bx = blockIdx.x * TW;
    const int by = blockIdx.y * TH;
    const bool interior = (blockIdx.x >= 1 && blockIdx.x <= 62 &&
                           blockIdx.y >= 1 && blockIdx.y <= 126);

    const float g0 = gauss[0], g1 = gauss[1], g2 = gauss[2],
                g3 = gauss[3], g4 = gauss[4];
    const ull G0 = packf2(g0, g0), G1 = packf2(g1, g1), G2 = packf2(g2, g2),
              G3 = packf2(g3, g3), G4 = packf2(g4, g4);

    // this thread's 4-wide x 2-tall output patch
    const int ox = 4 * (tid & 15);
    const int oy = 2 * (tid >> 4);

    // ---- S1 prefetch mapping: 720 float4 (40 rows x 18) ----
    const int s1r0 = tid / 18,          s1c0 = (tid - s1r0 * 18) * 4;
    const int t1 = tid + 256;
    const int s1r1 = t1 / 18,           s1c1 = (t1 - s1r1 * 18) * 4;
    const int t2s = tid + 512;
    const int s1r2 = t2s / 18,          s1c2 = (t2s - s1r2 * 18) * 4;
    const bool s1b2 = (t2s < 720);      // 208 threads

    // ---- S2 mapping: wide patches (1 row x 8 outputs), 320 items ----
    const int r20 = 8 * (tid >> 6) + (tid & 7);
    const int j20 = 8 * ((tid >> 3) & 7);
    const int i1  = tid + 256;                    // valid for tid < 64
    const int r21 = 8 * (i1 >> 6) + (i1 & 7);
    const int j21 = 8 * ((i1 >> 3) & 7);
    const bool s2b = (tid < 64);
    const bool s2n = (tid >= 192 && tid < 232);   // narrow col, rows 0..39
    const int rn = tid - 192;

    // ---- S3 mapping: 4-row x 1-col4 patches, 153 items ----
    const bool s3ok = (tid < 153);
    const int r3 = 4 * (tid / 17);
    const int j3 = 4 * (tid % 17);

    // ring pixel (mag coords: rows {1,34} x cols 0..65, cols {0,65} x rows 2..33)
    int mr = 1, mc = 0;
    const bool has_ring = (tid < 196);
    if (tid < 66)       { mr = 1;         mc = tid; }
    else if (tid < 132) { mr = 34;        mc = tid - 66; }
    else if (tid < 164) { mr = tid - 130; mc = 0; }
    else if (tid < 196) { mr = tid - 162; mc = 65; }

    float gxa[8], gya[8], maga[8];
    #pragma unroll
    for (int i = 0; i < 8; i++) { gxa[i] = 0.0f; gya[i] = 0.0f; maga[i] = 0.0f; }
    float ring_m = 0.0f;

    // ---- initial prefetch: channel 0 -> bufI0 ----
    if (interior) {
        const float* base = img + (size_t)(by - 4) * IMG_W + (bx - 4);
        cp_async16(&bufI0[s1r0 * SA + s1c0], base + (size_t)s1r0 * IMG_W + s1c0);
        cp_async16(&bufI0[s1r1 * SA + s1c1], base + (size_t)s1r1 * IMG_W + s1c1);
        if (s1b2)
            cp_async16(&bufI0[s1r2 * SA + s1c2], base + (size_t)s1r2 * IMG_W + s1c2);
        asm volatile("cp.async.commit_group;");
    } else {
        for (int p = tid; p < 2880; p += NT) {
            int r = p / 72;
            int cc = p - r * 72;
            int iy = by - 4 + r, ix = bx - 4 + cc;
            float v = 0.0f;
            if (iy >= 0 && iy < IMG_H && ix >= 0 && ix < IMG_W)
                v = img[(size_t)iy * IMG_W + ix];
            bufI0[r * SA + cc] = v;
        }
    }

    #pragma unroll
    for (int c = 0; c < 3; c++) {
        float* bI = (c & 1) ? bufI1 : bufI0;

        asm volatile("cp.async.wait_group 0;");
        __syncthreads();                 // bI ready; also orders prior channel's
                                         // S4/S4r reads before this channel's writes

        // ---- prefetch next channel ----
        if (c < 2) {
            float* bN = ((c + 1) & 1) ? bufI1 : bufI0;
            const float* imn = img + (size_t)(c + 1) * (IMG_H * IMG_W);
            if (interior) {
                const float* base = imn + (size_t)(by - 4) * IMG_W + (bx - 4);
                cp_async16(&bN[s1r0 * SA + s1c0], base + (size_t)s1r0 * IMG_W + s1c0);
                cp_async16(&bN[s1r1 * SA + s1c1], base + (size_t)s1r1 * IMG_W + s1c1);
                if (s1b2)
                    cp_async16(&bN[s1r2 * SA + s1c2], base + (size_t)s1r2 * IMG_W + s1c2);
                asm volatile("cp.async.commit_group;");
            } else {
                for (int p = tid; p < 2880; p += NT) {
                    int r = p / 72;
                    int cc = p - r * 72;
                    int iy = by - 4 + r, ix = bx - 4 + cc;
                    float v = 0.0f;
                    if (iy >= 0 && iy < IMG_H && ix >= 0 && ix < IMG_W)
                        v = imn[(size_t)iy * IMG_W + ix];
                    bN[r * SA + cc] = v;
                }
            }
        }

        // ---- S2: horizontal gaussian -> bufB (40 rows x 68 cols) ----
        {
            {
                const float* a = &bI[r20 * SA + j20];
                float4 v0 = *(const float4*)a;
                float4 v1 = *(const float4*)(a + 4);
                float4 v2 = *(const float4*)(a + 8);
                float w0=v0.x,w1=v0.y,w2=v0.z,w3=v0.w,w4=v1.x,w5=v1.y,w6=v1.z,w7=v1.w,
                      w8=v2.x,w9=v2.y,w10=v2.z,w11=v2.w;
                float4 o0, o1;
                o0.x = g0*w0 + g1*w1 + g2*w2 + g3*w3 + g4*w4;
                o0.y = g0*w1 + g1*w2 + g2*w3 + g3*w4 + g4*w5;
                o0.z = g0*w2 + g1*w3 + g2*w4 + g3*w5 + g4*w6;
                o0.w = g0*w3 + g1*w4 + g2*w5 + g3*w6 + g4*w7;
                o1.x = g0*w4 + g1*w5 + g2*w6 + g3*w7 + g4*w8;
                o1.y = g0*w5 + g1*w6 + g2*w7 + g3*w8 + g4*w9;
                o1.z = g0*w6 + g1*w7 + g2*w8 + g3*w9 + g4*w10;
                o1.w = g0*w7 + g1*w8 + g2*w9 + g3*w10 + g4*w11;
                *(float4*)&bufB[r20 * SBs + j20]     = o0;
                *(float4*)&bufB[r20 * SBs + j20 + 4] = o1;
            }
            if (s2b) {
                const float* a = &bI[r21 * SA + j21];
                float4 v0 = *(const float4*)a;
                float4 v1 = *(const float4*)(a + 4);
                float4 v2 = *(const float4*)(a + 8);
                float w0=v0.x,w1=v0.y,w2=v0.z,w3=v0.w,w4=v1.x,w5=v1.y,w6=v1.z,w7=v1.w,
                      w8=v2.x,w9=v2.y,w10=v2.z,w11=v2.w;
                float4 o0, o1;
                o0.x = g0*w0 + g1*w1 + g2*w2 + g3*w3 + g4*w4;
                o0.y = g0*w1 + g1*w2 + g2*w3 + g3*w4 + g4*w5;
                o0.z = g0*w2 + g1*w3 + g2*w4 + g3*w5 + g4*w6;
                o0.w = g0*w3 + g1*w4 + g2*w5 + g3*w6 + g4*w7;
                o1.x = g0*w4 + g1*w5 + g2*w6 + g3*w7 + g4*w8;
                o1.y = g0*w5 + g1*w6 + g2*w7 + g3*w8 + g4*w9;
                o1.z = g0*w6 + g1*w7 + g2*w8 + g3*w9 + g4*w10;
                o1.w = g0*w7 + g1*w8 + g2*w9 + g3*w10 + g4*w11;
                *(float4*)&bufB[r21 * SBs + j21]     = o0;
                *(float4*)&bufB[r21 * SBs + j21 + 4] = o1;
            }
            if (s2n) {
                const float* a = &bI[rn * SA + 64];
                float4 v0 = *(const float4*)a;
                float4 v1 = *(const float4*)(a + 4);
                float4 o0;
                o0.x = g0*v0.x + g1*v0.y + g2*v0.z + g3*v0.w + g4*v1.x;
                o0.y = g0*v0.y + g1*v0.z + g2*v0.w + g3*v1.x + g4*v1.y;
                o0.z = g0*v0.z + g1*v0.w + g2*v1.x + g3*v1.y + g4*v1.z;
                o0.w = g0*v0.w + g1*v1.x + g2*v1.y + g3*v1.z + g4*v1.w;
                *(float4*)&bufB[rn * SBs + 64] = o0;
            }
        }
        __syncthreads();

        // ---- S3: vertical gaussian -> bufBl (36 rows x 68 cols), 4-row patch ----
        if (s3ok) {
            const float* bcol = &bufB[r3 * SBs + j3];
            float* acol = &bufBl[r3 * SA + j3];
            if (interior) {
                // packed f32x2: 10 ops per float4 instead of 20
                ulonglong2 t0 = *(const ulonglong2*)(bcol);
                ulonglong2 t1 = *(const ulonglong2*)(bcol + 1 * SBs);
                ulonglong2 t2 = *(const ulonglong2*)(bcol + 2 * SBs);
                ulonglong2 t3 = *(const ulonglong2*)(bcol + 3 * SBs);
                ulonglong2 t4 = *(const ulonglong2*)(bcol + 4 * SBs);
                #pragma unroll
                for (int k = 0; k < 4; k++) {
                    ulonglong2 o;
                    o.x = pfma(G4, t4.x, pfma(G3, t3.x, pfma(G2, t2.x,
                              pfma(G1, t1.x, pmul(G0, t0.x)))));
                    o.y = pfma(G4, t4.y, pfma(G3, t3.y, pfma(G2, t2.y,
                              pfma(G1, t1.y, pmul(G0, t0.y)))));
                    *(ulonglong2*)(acol + k * SA) = o;
                    if (k < 3) {
                        t0 = t1; t1 = t2; t2 = t3; t3 = t4;
                        t4 = *(const ulonglong2*)(bcol + (5 + k) * SBs);
                    }
                }
            } else {
                float4 t0 = *(const float4*)(bcol);
                float4 t1 = *(const float4*)(bcol + 1 * SBs);
                float4 t2 = *(const float4*)(bcol + 2 * SBs);
                float4 t3 = *(const float4*)(bcol + 3 * SBs);
                float4 t4 = *(const float4*)(bcol + 4 * SBs);
                #pragma unroll
                for (int k = 0; k < 4; k++) {
                    float4 o = vblur5(g0, g1, g2, g3, g4, t0, t1, t2, t3, t4);
                    int iy = by - 2 + r3 + k;
                    int ixb = bx - 2 + j3;
                    float* po = &o.x;
                    #pragma unroll
                    for (int cc = 0; cc < 4; cc++) {
                        int ix = ixb + cc;
                        if (!(ix >= 0 && ix < IMG_W && iy >= 0 && iy < IMG_H)) po[cc] = 0.0f;
                    }
                    *(float4*)(acol + k * SA) = o;
                    if (k < 3) {
                        t0 = t1; t1 = t2; t2 = t3; t3 = t4;
                        t4 = *(const float4*)(bcol + (5 + k) * SBs);
                    }
                }
            }
        }
        __syncthreads();

        // ---- S4: sobel at output patch -> register accumulators ----
        {
            const float* b = &bufBl[(oy + 1) * SA + ox];
            float r0[8], r1[8], r2[8], r3v[8];
            {
                float4 lo, hi;
                lo = *(const float4*)(b);            hi = *(const float4*)(b + 4);
                r0[0]=lo.x; r0[1]=lo.y; r0[2]=lo.z; r0[3]=lo.w; r0[4]=hi.x; r0[5]=hi.y; r0[6]=hi.z; r0[7]=hi.w;
                lo = *(const float4*)(b + SA);       hi = *(const float4*)(b + SA + 4);
                r1[0]=lo.x; r1[1]=lo.y; r1[2]=lo.z; r1[3]=lo.w; r1[4]=hi.x; r1[5]=hi.y; r1[6]=hi.z; r1[7]=hi.w;
                lo = *(const float4*)(b + 2*SA);     hi = *(const float4*)(b + 2*SA + 4);
                r2[0]=lo.x; r2[1]=lo.y; r2[2]=lo.z; r2[3]=lo.w; r2[4]=hi.x; r2[5]=hi.y; r2[6]=hi.z; r2[7]=hi.w;
            }
            #pragma unroll
            for (int cc = 0; cc < 4; cc++) {
                float b00 = r0[cc+1], b01 = r0[cc+2], b02 = r0[cc+3];
                float b10 = r1[cc+1],                 b12 = r1[cc+3];
                float b20 = r2[cc+1], b21 = r2[cc+2], b22 = r2[cc+3];
                float gxv = (b00 - b02) + 2.0f * (b10 - b12) + (b20 - b22);
                float gyv = (b00 - b20) + 2.0f * (b01 - b21) + (b02 - b22);
                gxa[cc] += gxv;
                gya[cc] += gyv;
                maga[cc] += sqrtf(gxv * gxv + gyv * gyv + 1e-8f);
            }
            {
                float4 lo = *(const float4*)(b + 3*SA);
                float4 hi = *(const float4*)(b + 3*SA + 4);
                r3v[0]=lo.x; r3v[1]=lo.y; r3v[2]=lo.z; r3v[3]=lo.w; r3v[4]=hi.x; r3v[5]=hi.y; r3v[6]=hi.z; r3v[7]=hi.w;
            }
            #pragma unroll
            for (int cc = 0; cc < 4; cc++) {
                float b00 = r1[cc+1], b01 = r1[cc+2], b02 = r1[cc+3];
                float b10 = r2[cc+1],                 b12 = r2[cc+3];
                float b20 = r3v[cc+1], b21 = r3v[cc+2], b22 = r3v[cc+3];
                float gxv = (b00 - b02) + 2.0f * (b10 - b12) + (b20 - b22);
                float gyv = (b00 - b20) + 2.0f * (b01 - b21) + (b02 - b22);
                gxa[4+cc] += gxv;
                gya[4+cc] += gyv;
                maga[4+cc] += sqrtf(gxv * gxv + gyv * gyv + 1e-8f);
            }
        }

        // ---- S4r: halo-ring mag pixel (register accumulated) ----
        if (has_ring) {
            const float* b = &bufBl[(mr - 1) * SA + mc];
            float b00 = b[0],      b01 = b[1],          b02 = b[2];
            float b10 = b[SA],                          b12 = b[SA + 2];
            float b20 = b[2 * SA], b21 = b[2 * SA + 1], b22 = b[2 * SA + 2];
            float gxv = (b00 - b02) + 2.0f * (b10 - b12) + (b20 - b22);
            float gyv = (b00 - b20) + 2.0f * (b01 - b21) + (b02 - b22);
            float m = sqrtf(gxv * gxv + gyv * gyv + 1e-8f);
            if (!interior) {
                int iy = by - 2 + mr, ix = bx - 1 + mc;
                if (iy < 0 || iy >= IMG_H || ix < 0 || ix >= IMG_W) m = 0.0f;
            }
            ring_m += m;
        }
        // NOTE: no end-of-channel barrier. The loop-top __syncthreads (next
        // iteration) orders this channel's bufBl/bufB reads against the next
        // channel's S2/S3 writes; after the last channel, the publish below
        // writes bufM (= bufI0), disjoint from bufBl, and bufI0's last reads
        // (S2 of c=2) completed before the post-S2 barrier.
    }

    // ---- publish mag to shared (bufM aliases bufI0; dead now) ----
    #pragma unroll
    for (int rr = 0; rr < 2; rr++) {
        *(float4*)&bufM[(oy + 1 + rr) * SMs + ox + 4] =
            make_float4(maga[rr*4], maga[rr*4+1], maga[rr*4+2], maga[rr*4+3]);
    }
    if (has_ring) bufM[(mr - 1) * SMs + mc + 3] = ring_m;
    __syncthreads();

    // ---- S5: orientation, NMS, threshold, write ----
    const unsigned DYP = 0x00012221u;   // nibble ip -> dy+1
    const unsigned DXP = 0x21000122u;   // nibble ip -> dx+1
    const float RAD2DEG = (float)(180.0 / 3.14159);

    #pragma unroll
    for (int rr = 0; rr < 2; rr++) {
        float ov[4];
        #pragma unroll
        for (int cc = 0; cc < 4; cc++) {
            int y = oy + rr, x = ox + cc;
            float m  = maga[rr*4+cc];
            float t = atan2f(gya[rr*4+cc], gxa[rr*4+cc]) * RAD2DEG + 180.0f;
            int k = (int)rintf(t / 45.0f);
            int ip = k & 7;
            int dy = (int)((DYP >> (ip * 4)) & 7u) - 1;
            int dx = (int)((DXP >> (ip * 4)) & 7u) - 1;
            float mp = bufM[(y + 1 + dy) * SMs + (x + 4 + dx)];
            float mn = bufM[(y + 1 - dy) * SMs + (x + 4 - dx)];
            bool is_max = fminf(m - mp, m - mn) > 0.0f;
            ov[cc] = (is_max && m >= 6.0f && m <= 50.0f) ? 1.0f : 0.0f;
        }
        *(float4*)(out + (size_t)(by + oy + rr) * IMG_W + bx + ox) =
            make_float4(ov[0], ov[1], ov[2], ov[3]);
    }
}

extern "C" void kernel_launch(void* const* d_in, const int* in_sizes, int n_in,
                              void* d_out, int out_size) {
    const float* img   = (const float*)d_in[0];  // [1,3,4096,4096]
    const float* gauss = (const float*)d_in[1];  // [5]
    float* out = (float*)d_out;                  // [1,1,4096,4096]

    dim3 grid(IMG_W / TW, IMG_H / TH);
    canny_kernel<<<grid, NT>>>(img, gauss, out);
}